// round 13
// baseline (speedup 1.0000x reference)
#include <cuda_runtime.h>
#include <cuda_fp16.h>
#include <cstdint>

#define HIDDEN    450
#define ATOM_FDIM 35
#define MAX_NB    15

#define LDC     512          // fp32 activation stride (rows 2048B, 128B aligned)
#define KB_PAD  464          // 450 -> 29*16
#define KI_PAD  48           // 40  -> 3*16
#define KO_PAD  496          // 485 -> 31*16 (layout: [nei 450 | fatoms 35 | pad])
#define MB_PAD  40064        // 313*128
#define MA_PAD  20096        // 157*128
#define NW      512          // weight rows padded

// tile: 128 (M) x 160 (N), grid.x = 3 -> N covered = 480 (>=456 needed)
#define BN      160
// smem stage layout (u32 offsets): Ahh[128x12] All[128x12] Bhh[160x12] Bll[160x12]
#define OFF_AHH 0
#define OFF_ALL 1536
#define OFF_BHH 3072
#define OFF_BLL 4992
#define STAGE_WORDS 6912
#define SMEM_BYTES  (2 * STAGE_WORDS * 4)     // 55296 -> 2 CTAs/SM
#define N_CHUNKS 1152                          // 16B cp.async chunks per stage

// ---------------- scratch (device globals; .bss zero => padding zero) --------
__device__ float    g_binput[(size_t)MB_PAD * LDC];
__device__ float    g_gmsg  [(size_t)MB_PAD * LDC];
__device__ uint32_t g_neiHH[(size_t)MB_PAD * (KB_PAD/2)];
__device__ uint32_t g_neiLL[(size_t)MB_PAD * (KB_PAD/2)];
__device__ uint32_t g_atHH [(size_t)MA_PAD * (KO_PAD/2)];
__device__ uint32_t g_atLL [(size_t)MA_PAD * (KO_PAD/2)];
__device__ uint32_t g_fbHH [(size_t)MB_PAD * (KI_PAD/2)];
__device__ uint32_t g_fbLL [(size_t)MB_PAD * (KI_PAD/2)];
__device__ uint32_t g_WiHH[NW * (KI_PAD/2)], g_WiLL[NW * (KI_PAD/2)];
__device__ uint32_t g_WhHH[NW * (KB_PAD/2)], g_WhLL[NW * (KB_PAD/2)];
__device__ uint32_t g_WoHH[NW * (KO_PAD/2)], g_WoLL[NW * (KO_PAD/2)];

// ---------------- helpers -----------------------------------------------------
__device__ __forceinline__ void split_h(float v, uint32_t& h, uint32_t& l) {
    __half hh = __float2half_rn(v);
    float  hf = __half2float(hh);
    __half ll = __float2half_rn(v - hf);
    h = (uint32_t)__half_as_ushort(hh);
    l = (uint32_t)__half_as_ushort(ll);
}

__device__ __forceinline__ uint32_t prmt(uint32_t a, uint32_t b, uint32_t s) {
    uint32_t r;
    asm("prmt.b32 %0, %1, %2, %3;" : "=r"(r) : "r"(a), "r"(b), "r"(s));
    return r;
}

__device__ __forceinline__ void mma_f16(float* c, const uint32_t* a, uint32_t b0, uint32_t b1) {
    asm volatile(
        "mma.sync.aligned.m16n8k16.row.col.f32.f16.f16.f32 "
        "{%0,%1,%2,%3},{%4,%5,%6,%7},{%8,%9},{%0,%1,%2,%3};"
        : "+f"(c[0]), "+f"(c[1]), "+f"(c[2]), "+f"(c[3])
        : "r"(a[0]), "r"(a[1]), "r"(a[2]), "r"(a[3]), "r"(b0), "r"(b1));
}

// ---------------- pre-split kernel (hh + ll packs; side-agnostic) -------------
__global__ __launch_bounds__(256)
void split_pack(const float* __restrict__ src, int ld_src, int rows, int cols,
                uint32_t* __restrict__ hh, uint32_t* __restrict__ ll,
                int ldh, int dstk0 /* even */)
{
    const int npair = (cols + 1) >> 1;
    int i = blockIdx.x * blockDim.x + threadIdx.x;
    if (i >= rows * npair) return;
    int r = i / npair, jj = i - r * npair;
    int k0 = 2 * jj, k1 = k0 + 1;
    float v0 = src[(size_t)r * ld_src + k0];
    float v1 = (k1 < cols) ? src[(size_t)r * ld_src + k1] : 0.f;
    uint32_t h0, l0, h1, l1;
    split_h(v0, h0, l0);
    split_h(v1, h1, l1);
    size_t o = (size_t)r * ldh + (dstk0 >> 1) + jj;
    hh[o] = h0 | (h1 << 16);
    ll[o] = l0 | (l1 << 16);
}

// ---------------- gather + split ---------------------------------------------
__global__ __launch_bounds__(256)
void gather_split(const int* __restrict__ graph,
                  const float* __restrict__ tree, int n_mess,
                  const float* __restrict__ gmsg,
                  uint32_t* __restrict__ hh, uint32_t* __restrict__ ll, int ldh)
{
    const int b = blockIdx.x;
    __shared__ const float* rows[MAX_NB];
    if (threadIdx.x < MAX_NB) {
        int id = graph[(size_t)b * MAX_NB + threadIdx.x];
        rows[threadIdx.x] = (id < n_mess) ? (tree + (size_t)id * HIDDEN)
                                          : (gmsg + (size_t)(id - n_mess) * LDC);
    }
    __syncthreads();
    const int t = threadIdx.x;
    if (t < HIDDEN / 2) {
        float2 acc = make_float2(0.f, 0.f);
#pragma unroll
        for (int nb = 0; nb < MAX_NB; nb++) {
            float2 v = ((const float2*)rows[nb])[t];
            acc.x += v.x; acc.y += v.y;
        }
        uint32_t h0, l0, h1, l1;
        split_h(acc.x, h0, l0);
        split_h(acc.y, h1, l1);
        size_t o = (size_t)b * ldh + t;
        hh[o] = h0 | (h1 << 16);
        ll[o] = l0 | (l1 << 16);
    }
}

// ---------------- pipelined fp16 3-term GEMM (128x160, hh/ll + PRMT) ---------
// per 16 original k: 1 hh k16 MMA + 2 cross k16 MMAs; cross fragments built
// in-register: A slot pair {Ah,Al}, W slot pair {Wl,Wh} via PRMT.
// MODE 0: C = t, C2 = relu(t);  MODE 1: C = relu(t + biasM);  MODE 2: relu(t + biasV[n])
template <int MODE>
__global__ __launch_bounds__(256, 2)
void mma_gemm(const uint32_t* __restrict__ AHH, const uint32_t* __restrict__ ALL,
              const uint32_t* __restrict__ WHH, const uint32_t* __restrict__ WLL,
              int ldh, int nK,
              const float* __restrict__ biasM, const float* __restrict__ biasV,
              float* __restrict__ C, float* __restrict__ C2)
{
    extern __shared__ uint32_t sm[];
    const unsigned sbase = (unsigned)__cvta_generic_to_shared(sm);

    const int tid  = threadIdx.x;
    const int lane = tid & 31;
    const int wid  = tid >> 5;
    const int wm   = wid & 3;          // 4 warps along M (32 rows each)
    const int wn   = wid >> 2;         // 2 warps along N (80 cols each)
    const int row0 = blockIdx.y * 128;
    const int col0 = blockIdx.x * BN;

    float acc[2][10][4];
#pragma unroll
    for (int a = 0; a < 2; a++)
#pragma unroll
        for (int b = 0; b < 10; b++)
#pragma unroll
            for (int q = 0; q < 4; q++) acc[a][b][q] = 0.f;

    // stage fill: 1152 16B chunks, 8 u32 per row for each of 4 arrays
    auto issue = [&](int stage, int kt) {
        const unsigned sb = sbase + stage * (STAGE_WORDS * 4);
        const int kh0 = kt * 8;
#pragma unroll
        for (int i = 0; i < 5; i++) {
            int p = i * 256 + tid;
            if (p >= N_CHUNKS) break;
            const uint32_t* g;
            unsigned d;
            if (p < 256) {                     // Ahh: 128 rows x 2 chunks
                int row = p >> 1, q = p & 1;
                g = AHH + (size_t)(row0 + row) * ldh + kh0 + q * 4;
                d = sb + (unsigned)(OFF_AHH + row * 12 + q * 4) * 4u;
            } else if (p < 512) {              // All
                int pp = p - 256;
                int row = pp >> 1, q = pp & 1;
                g = ALL + (size_t)(row0 + row) * ldh + kh0 + q * 4;
                d = sb + (unsigned)(OFF_ALL + row * 12 + q * 4) * 4u;
            } else if (p < 832) {              // Bhh: 160 rows x 2 chunks
                int pp = p - 512;
                int row = pp >> 1, q = pp & 1;
                g = WHH + (size_t)(col0 + row) * ldh + kh0 + q * 4;
                d = sb + (unsigned)(OFF_BHH + row * 12 + q * 4) * 4u;
            } else {                           // Bll
                int pp = p - 832;
                int row = pp >> 1, q = pp & 1;
                g = WLL + (size_t)(col0 + row) * ldh + kh0 + q * 4;
                d = sb + (unsigned)(OFF_BLL + row * 12 + q * 4) * 4u;
            }
            asm volatile("cp.async.cg.shared.global [%0], [%1], 16;\n" :: "r"(d), "l"(g));
        }
        asm volatile("cp.async.commit_group;\n");
    };

    issue(0, 0);

    for (int kt = 0; kt < nK; kt++) {
        if (kt + 1 < nK) {
            issue((kt + 1) & 1, kt + 1);
            asm volatile("cp.async.wait_group 1;\n");
        } else {
            asm volatile("cp.async.wait_group 0;\n");
        }
        __syncthreads();

        const uint32_t* S = sm + (kt & 1) * STAGE_WORDS;
        const uint32_t* sAhh = S + OFF_AHH;
        const uint32_t* sAll = S + OFF_ALL;
        const uint32_t* sBhh = S + OFF_BHH;
        const uint32_t* sBll = S + OFF_BLL;

        // ---- hh: one k16 MMA covers all 16 original k
        {
            const int kc = lane & 3;
            uint32_t aH[2][4];
#pragma unroll
            for (int mt = 0; mt < 2; mt++) {
                int r = wm * 32 + mt * 16 + (lane >> 2);
                const uint32_t* p = sAhh + r * 12 + kc;
                aH[mt][0] = p[0]; aH[mt][1] = p[96]; aH[mt][2] = p[4]; aH[mt][3] = p[100];
            }
#pragma unroll
            for (int nt = 0; nt < 10; nt++) {
                int n = wn * 80 + nt * 8 + (lane >> 2);
                const uint32_t* p = sBhh + n * 12 + kc;
                uint32_t b0 = p[0], b1 = p[4];
#pragma unroll
                for (int mt = 0; mt < 2; mt++)
                    mma_f16(acc[mt][nt], aH[mt], b0, b1);
            }
        }

        // ---- cross: two k16 MMAs; fragments via PRMT from hh/ll
        const uint32_t selA = (lane & 1) ? 0x7632u : 0x5410u;  // A: {h,l}
        const uint32_t selB = (lane & 1) ? 0x3276u : 0x1054u;  // W: {l,h}
#pragma unroll
        for (int ks = 0; ks < 2; ks++) {
            const int w1 = ks * 4 + ((lane & 3) >> 1);   // word of orig K = 8ks + kc
            uint32_t aX[2][4];
#pragma unroll
            for (int mt = 0; mt < 2; mt++) {
                int r = wm * 32 + mt * 16 + (lane >> 2);
                const uint32_t* ph = sAhh + r * 12 + w1;
                const uint32_t* pl = sAll + r * 12 + w1;
                aX[mt][0] = prmt(ph[0],  pl[0],  selA);
                aX[mt][1] = prmt(ph[96], pl[96], selA);   // row + 8
                aX[mt][2] = prmt(ph[2],  pl[2],  selA);   // K + 4
                aX[mt][3] = prmt(ph[98], pl[98], selA);
            }
#pragma unroll
            for (int nt = 0; nt < 10; nt++) {
                int n = wn * 80 + nt * 8 + (lane >> 2);
                const uint32_t* ph = sBhh + n * 12 + w1;
                const uint32_t* pl = sBll + n * 12 + w1;
                uint32_t b0 = prmt(ph[0], pl[0], selB);
                uint32_t b1 = prmt(ph[2], pl[2], selB);
#pragma unroll
                for (int mt = 0; mt < 2; mt++)
                    mma_f16(acc[mt][nt], aX[mt], b0, b1);
            }
        }
        __syncthreads();
    }

    // epilogue (rows padded; cols < 480 <= LDC, padded cols harmless)
#pragma unroll
    for (int mt = 0; mt < 2; mt++) {
#pragma unroll
        for (int h = 0; h < 2; h++) {
            int r = row0 + wm * 32 + mt * 16 + (lane >> 2) + h * 8;
#pragma unroll
            for (int nt = 0; nt < 10; nt++) {
                int c = col0 + wn * 80 + nt * 8 + 2 * (lane & 3);
                float x = acc[mt][nt][h * 2 + 0];
                float y = acc[mt][nt][h * 2 + 1];
                size_t o = (size_t)r * LDC + c;
                if (MODE == 0) {
                    *(float2*)(C + o)  = make_float2(x, y);
                    *(float2*)(C2 + o) = make_float2(x > 0.f ? x : 0.f, y > 0.f ? y : 0.f);
                } else if (MODE == 1) {
                    float2 bm = *(const float2*)(biasM + o);
                    x += bm.x; y += bm.y;
                    *(float2*)(C + o) = make_float2(x > 0.f ? x : 0.f, y > 0.f ? y : 0.f);
                } else {
                    x += (c     < HIDDEN) ? biasV[c]     : 0.f;
                    y += (c + 1 < HIDDEN) ? biasV[c + 1] : 0.f;
                    *(float2*)(C + o) = make_float2(x > 0.f ? x : 0.f, y > 0.f ? y : 0.f);
                }
            }
        }
    }
}

// ---------------- per-molecule mean -----------------------------------------
__global__ __launch_bounds__(256)
void mol_mean_kernel(const float* __restrict__ ah, const int* __restrict__ mol_ids,
                     int n_atoms, float* __restrict__ out)
{
    const int m = blockIdx.x;
    __shared__ int s_start, s_end;
    if (threadIdx.x == 0) {
        int lo = 0, hi = n_atoms;
        while (lo < hi) { int mid = (lo + hi) >> 1; if (mol_ids[mid] <  m) lo = mid + 1; else hi = mid; }
        s_start = lo;
        lo = 0; hi = n_atoms;
        while (lo < hi) { int mid = (lo + hi) >> 1; if (mol_ids[mid] <= m) lo = mid + 1; else hi = mid; }
        s_end = lo;
    }
    __syncthreads();
    const int start = s_start;
    const int cnt   = s_end - s_start;
    const float inv = cnt > 0 ? 1.f / (float)cnt : 0.f;

    for (int h = threadIdx.x; h < HIDDEN; h += blockDim.x) {
        float s = 0.f;
        for (int a = 0; a < cnt; a++)
            s += ah[(size_t)(start + a) * LDC + h];
        out[(size_t)m * HIDDEN + h] = s * inv;
    }
}

// ---------------- launch ----------------------------------------------------
extern "C" void kernel_launch(void* const* d_in, const int* in_sizes, int n_in,
                              void* d_out, int out_size)
{
    const float* fatoms  = (const float*)d_in[0];
    const float* fbonds  = (const float*)d_in[1];
    const int*   agraph  = (const int*)d_in[2];
    const int*   bgraph  = (const int*)d_in[3];
    const int*   mol_ids = (const int*)d_in[4];
    const float* tree    = (const float*)d_in[6];
    const float* W_i     = (const float*)d_in[7];
    const float* W_h     = (const float*)d_in[8];
    const float* W_o     = (const float*)d_in[9];
    const float* b_o     = (const float*)d_in[10];
    float* out = (float*)d_out;

    const int n_atoms = in_sizes[0] / ATOM_FDIM;
    const int n_bonds = in_sizes[1] / (ATOM_FDIM + 5);
    const int n_mess  = in_sizes[6] / HIDDEN;
    const int n_mols  = out_size / HIDDEN;
    const int IN_FDIM = ATOM_FDIM + 5;       // 40
    const int OUT_K   = ATOM_FDIM + HIDDEN;  // 485 (src W_o ld)

    float *binput, *gmsg;
    uint32_t *neiHH, *neiLL, *atHH, *atLL, *fbHH, *fbLL;
    uint32_t *WiHH, *WiLL, *WhHH, *WhLL, *WoHH, *WoLL;
    cudaGetSymbolAddress((void**)&binput, g_binput);
    cudaGetSymbolAddress((void**)&gmsg,   g_gmsg);
    cudaGetSymbolAddress((void**)&neiHH,  g_neiHH);
    cudaGetSymbolAddress((void**)&neiLL,  g_neiLL);
    cudaGetSymbolAddress((void**)&atHH,   g_atHH);
    cudaGetSymbolAddress((void**)&atLL,   g_atLL);
    cudaGetSymbolAddress((void**)&fbHH,   g_fbHH);
    cudaGetSymbolAddress((void**)&fbLL,   g_fbLL);
    cudaGetSymbolAddress((void**)&WiHH,   g_WiHH);
    cudaGetSymbolAddress((void**)&WiLL,   g_WiLL);
    cudaGetSymbolAddress((void**)&WhHH,   g_WhHH);
    cudaGetSymbolAddress((void**)&WhLL,   g_WhLL);
    cudaGetSymbolAddress((void**)&WoHH,   g_WoHH);
    cudaGetSymbolAddress((void**)&WoLL,   g_WoLL);

    cudaFuncSetAttribute(mma_gemm<0>, cudaFuncAttributeMaxDynamicSharedMemorySize, SMEM_BYTES);
    cudaFuncSetAttribute(mma_gemm<1>, cudaFuncAttributeMaxDynamicSharedMemorySize, SMEM_BYTES);
    cudaFuncSetAttribute(mma_gemm<2>, cudaFuncAttributeMaxDynamicSharedMemorySize, SMEM_BYTES);

    dim3 blk(256);
    const int mb = (n_bonds + 127) / 128;   // 313
    const int ma = (n_atoms + 127) / 128;   // 157
    dim3 grid_b(3, mb), grid_a(3, ma);      // 3 x 160 = 480 cols

    // ---- pre-split inputs & weights (hh + ll packs)
    split_pack<<<(n_bonds * ((IN_FDIM + 1) / 2) + 255) / 256, blk>>>(
        fbonds, IN_FDIM, n_bonds, IN_FDIM, fbHH, fbLL, KI_PAD / 2, 0);
    split_pack<<<(HIDDEN * ((IN_FDIM + 1) / 2) + 255) / 256, blk>>>(
        W_i, IN_FDIM, HIDDEN, IN_FDIM, WiHH, WiLL, KI_PAD / 2, 0);
    split_pack<<<(HIDDEN * ((HIDDEN + 1) / 2) + 255) / 256, blk>>>(
        W_h, HIDDEN, HIDDEN, HIDDEN, WhHH, WhLL, KB_PAD / 2, 0);
    // W_o permuted: [nei 450 | fatoms 35]
    split_pack<<<(HIDDEN * ((HIDDEN + 1) / 2) + 255) / 256, blk>>>(
        W_o + ATOM_FDIM, OUT_K, HIDDEN, HIDDEN, WoHH, WoLL, KO_PAD / 2, 0);
    split_pack<<<(HIDDEN * ((ATOM_FDIM + 1) / 2) + 255) / 256, blk>>>(
        W_o, OUT_K, HIDDEN, ATOM_FDIM, WoHH, WoLL, KO_PAD / 2, HIDDEN);
    // fatoms at k-offset 450
    split_pack<<<(n_atoms * ((ATOM_FDIM + 1) / 2) + 255) / 256, blk>>>(
        fatoms, ATOM_FDIM, n_atoms, ATOM_FDIM, atHH, atLL, KO_PAD / 2, HIDDEN);

    // ---- init layer: binput = fbonds @ W_i^T ; gmsg = relu(binput)
    mma_gemm<0><<<grid_b, blk, SMEM_BYTES>>>(fbHH, fbLL, WiHH, WiLL, KI_PAD / 2, KI_PAD / 16,
                                             nullptr, nullptr, binput, gmsg);

    // ---- 5 message-passing steps
    for (int it = 0; it < 5; it++) {
        gather_split<<<n_bonds, blk>>>(bgraph, tree, n_mess, gmsg, neiHH, neiLL, KB_PAD / 2);
        mma_gemm<1><<<grid_b, blk, SMEM_BYTES>>>(neiHH, neiLL, WhHH, WhLL, KB_PAD / 2, KB_PAD / 16,
                                                 binput, nullptr, gmsg, nullptr);
    }

    // ---- atom aggregation (nei at k 0..449) + output layer
    gather_split<<<n_atoms, blk>>>(agraph, tree, n_mess, gmsg, atHH, atLL, KO_PAD / 2);
    mma_gemm<2><<<grid_a, blk, SMEM_BYTES>>>(atHH, atLL, WoHH, WoLL, KO_PAD / 2, KO_PAD / 16,
                                             nullptr, b_o, binput, nullptr);

    // ---- per-molecule mean
    mol_mean_kernel<<<n_mols, blk>>>(binput, mol_ids, n_atoms, out);
}

// round 14
// speedup vs baseline: 1.1441x; 1.1441x over previous
#include <cuda_runtime.h>
#include <cuda_fp16.h>
#include <cstdint>

#define HIDDEN    450
#define ATOM_FDIM 35
#define MAX_NB    15

#define LDC     512          // fp32 activation stride (rows 2048B, 128B aligned)
#define KB_PAD  464          // 450 -> 29*16
#define KI_PAD  48           // 40  -> 3*16
#define KO_PAD  496          // 485 -> 31*16 (layout: [nei 450 | fatoms 35 | pad])
#define MB_PAD  40064        // 313*128
#define MA_PAD  20096        // 157*128
#define NW      512          // weight rows padded

// tile: 128 (M) x 160 (N), grid.x = 3 -> N covered = 480 (>=456 needed)
#define BN      160
// smem stage layout (u32 offsets): Ahh[128x12] Bhh[160x12] Ax[128x20] Bx[160x20]
#define OFF_AHH 0
#define OFF_BHH 1536
#define OFF_AX  3456
#define OFF_BX  6016
#define STAGE_WORDS 9216
#define SMEM_BYTES  (3 * STAGE_WORDS * 4)     // 110592/CTA; 2 CTAs = 221KB <= 228KB
#define N_CHUNKS 1728                          // 16B cp.async chunks per stage

// ---------------- scratch (device globals; .bss zero => padding zero) --------
__device__ float    g_binput[(size_t)MB_PAD * LDC];
__device__ float    g_gmsg  [(size_t)MB_PAD * LDC];
__device__ uint32_t g_neiHH[(size_t)MB_PAD * (KB_PAD/2)];
__device__ uint32_t g_neiX [(size_t)MB_PAD * KB_PAD];
__device__ uint32_t g_atHH [(size_t)MA_PAD * (KO_PAD/2)];
__device__ uint32_t g_atX  [(size_t)MA_PAD * KO_PAD];
__device__ uint32_t g_fbHH [(size_t)MB_PAD * (KI_PAD/2)];
__device__ uint32_t g_fbX  [(size_t)MB_PAD * KI_PAD];
__device__ uint32_t g_WiHH[NW * (KI_PAD/2)], g_WiX[NW * KI_PAD];
__device__ uint32_t g_WhHH[NW * (KB_PAD/2)], g_WhX[NW * KB_PAD];
__device__ uint32_t g_WoHH[NW * (KO_PAD/2)], g_WoX[NW * KO_PAD];

// ---------------- fp16 split helpers -----------------------------------------
__device__ __forceinline__ void split_h(float v, uint32_t& h, uint32_t& l) {
    __half hh = __float2half_rn(v);
    float  hf = __half2float(hh);
    __half ll = __float2half_rn(v - hf);
    h = (uint32_t)__half_as_ushort(hh);
    l = (uint32_t)__half_as_ushort(ll);
}

__device__ __forceinline__ void mma_f16(float* c, const uint32_t* a, uint32_t b0, uint32_t b1) {
    asm volatile(
        "mma.sync.aligned.m16n8k16.row.col.f32.f16.f16.f32 "
        "{%0,%1,%2,%3},{%4,%5,%6,%7},{%8,%9},{%0,%1,%2,%3};"
        : "+f"(c[0]), "+f"(c[1]), "+f"(c[2]), "+f"(c[3])
        : "r"(a[0]), "r"(a[1]), "r"(a[2]), "r"(a[3]), "r"(b0), "r"(b1));
}

// ---------------- pre-split kernel ------------------------------------------
// SIDE 0 (A): x-pack = {lo16: hi, hi16: lo};  SIDE 1 (W): x-pack = {lo16: lo, hi16: hi}
template <int SIDE>
__global__ __launch_bounds__(256)
void split_pack(const float* __restrict__ src, int ld_src, int rows, int cols,
                uint32_t* __restrict__ hh, uint32_t* __restrict__ xx,
                int ldx, int dstk0 /* even */)
{
    const int npair = (cols + 1) >> 1;
    int i = blockIdx.x * blockDim.x + threadIdx.x;
    if (i >= rows * npair) return;
    int r = i / npair, jj = i - r * npair;
    int k0 = 2 * jj, k1 = k0 + 1;
    float v0 = src[(size_t)r * ld_src + k0];
    float v1 = (k1 < cols) ? src[(size_t)r * ld_src + k1] : 0.f;
    uint32_t h0, l0, h1, l1;
    split_h(v0, h0, l0);
    split_h(v1, h1, l1);
    const int ldh = ldx >> 1;
    hh[(size_t)r * ldh + (dstk0 >> 1) + jj] = h0 | (h1 << 16);
    size_t ox = (size_t)r * ldx + dstk0 + k0;
    if (SIDE == 0) {
        xx[ox]     = h0 | (l0 << 16);
        xx[ox + 1] = h1 | (l1 << 16);
    } else {
        xx[ox]     = l0 | (h0 << 16);
        xx[ox + 1] = l1 | (h1 << 16);
    }
}

// ---------------- gather + split (A side, dst k-offset 0) --------------------
__global__ __launch_bounds__(256)
void gather_split(const int* __restrict__ graph,
                  const float* __restrict__ tree, int n_mess,
                  const float* __restrict__ gmsg,
                  uint32_t* __restrict__ hh, uint32_t* __restrict__ xx, int ldx)
{
    const int b = blockIdx.x;
    __shared__ const float* rows[MAX_NB];
    if (threadIdx.x < MAX_NB) {
        int id = graph[(size_t)b * MAX_NB + threadIdx.x];
        rows[threadIdx.x] = (id < n_mess) ? (tree + (size_t)id * HIDDEN)
                                          : (gmsg + (size_t)(id - n_mess) * LDC);
    }
    __syncthreads();
    const int t = threadIdx.x;
    if (t < HIDDEN / 2) {
        float2 acc = make_float2(0.f, 0.f);
#pragma unroll
        for (int nb = 0; nb < MAX_NB; nb++) {
            float2 v = ((const float2*)rows[nb])[t];
            acc.x += v.x; acc.y += v.y;
        }
        uint32_t h0, l0, h1, l1;
        split_h(acc.x, h0, l0);
        split_h(acc.y, h1, l1);
        hh[(size_t)b * (ldx >> 1) + t] = h0 | (h1 << 16);
        size_t ox = (size_t)b * ldx + 2 * t;
        xx[ox]     = h0 | (l0 << 16);
        xx[ox + 1] = h1 | (l1 << 16);
    }
}

// ---------------- pipelined fp16 3-term GEMM (128x160, 3-stage, 1 barrier) ---
// per 16 original k: 1 hh k16 MMA + 2 cross k16 MMAs (per warp n-tile)
// MODE 0: C = t, C2 = relu(t);  MODE 1: C = relu(t + biasM);  MODE 2: relu(t + biasV[n])
template <int MODE>
__global__ __launch_bounds__(256, 2)
void mma_gemm(const uint32_t* __restrict__ AHH, const uint32_t* __restrict__ AX,
              const uint32_t* __restrict__ WHH, const uint32_t* __restrict__ WX,
              int ldx, int nK,
              const float* __restrict__ biasM, const float* __restrict__ biasV,
              float* __restrict__ C, float* __restrict__ C2)
{
    extern __shared__ uint32_t sm[];
    const unsigned sbase = (unsigned)__cvta_generic_to_shared(sm);
    const int ldh = ldx >> 1;

    const int tid  = threadIdx.x;
    const int lane = tid & 31;
    const int wid  = tid >> 5;
    const int wm   = wid & 3;          // 4 warps along M (32 rows each)
    const int wn   = wid >> 2;         // 2 warps along N (80 cols each)
    const int row0 = blockIdx.y * 128;
    const int col0 = blockIdx.x * BN;

    float acc[2][10][4];
#pragma unroll
    for (int a = 0; a < 2; a++)
#pragma unroll
        for (int b = 0; b < 10; b++)
#pragma unroll
            for (int q = 0; q < 4; q++) acc[a][b][q] = 0.f;

    // stage fill: 1728 16B chunks, 7 iters (last partial)
    auto issue = [&](int stage, int kt) {
        const unsigned sb = sbase + stage * (STAGE_WORDS * 4);
        const int kh0 = kt * 8;
        const int kx0 = kt * 16;
#pragma unroll
        for (int i = 0; i < 7; i++) {
            int p = i * 256 + tid;
            if (p >= N_CHUNKS) break;
            const uint32_t* g;
            unsigned d;
            if (p < 256) {                     // Ahh: 128 rows x 2 chunks
                int row = p >> 1, q = p & 1;
                g = AHH + (size_t)(row0 + row) * ldh + kh0 + q * 4;
                d = sb + (unsigned)(OFF_AHH + row * 12 + q * 4) * 4u;
            } else if (p < 576) {              // Bhh: 160 rows x 2 chunks
                int pp = p - 256;
                int row = pp >> 1, q = pp & 1;
                g = WHH + (size_t)(col0 + row) * ldh + kh0 + q * 4;
                d = sb + (unsigned)(OFF_BHH + row * 12 + q * 4) * 4u;
            } else if (p < 1088) {             // Ax: 128 rows x 4 chunks
                int pp = p - 576;
                int row = pp >> 2, q = pp & 3;
                g = AX + (size_t)(row0 + row) * ldx + kx0 + q * 4;
                d = sb + (unsigned)(OFF_AX + row * 20 + q * 4) * 4u;
            } else {                           // Bx: 160 rows x 4 chunks
                int pp = p - 1088;
                int row = pp >> 2, q = pp & 3;
                g = WX + (size_t)(col0 + row) * ldx + kx0 + q * 4;
                d = sb + (unsigned)(OFF_BX + row * 20 + q * 4) * 4u;
            }
            asm volatile("cp.async.cg.shared.global [%0], [%1], 16;\n" :: "r"(d), "l"(g));
        }
        asm volatile("cp.async.commit_group;\n");
    };

    issue(0, 0);
    issue(1, 1);          // nK >= 3 for all layers

    for (int kt = 0; kt < nK; kt++) {
        asm volatile("cp.async.wait_group 1;\n");   // stage kt resident
        __syncthreads();                            // all warps done with stage kt-1

        if (kt + 2 < nK) issue((kt + 2) % 3, kt + 2);
        else             asm volatile("cp.async.commit_group;\n");

        const uint32_t* S = sm + (kt % 3) * STAGE_WORDS;
        const uint32_t* sAhh = S + OFF_AHH;
        const uint32_t* sBhh = S + OFF_BHH;
        const uint32_t* sAx  = S + OFF_AX;
        const uint32_t* sBx  = S + OFF_BX;

        // ---- hh: one k16 MMA covers all 16 original k
        {
            const int kc = lane & 3;
            uint32_t aH[2][4];
#pragma unroll
            for (int mt = 0; mt < 2; mt++) {
                int r = wm * 32 + mt * 16 + (lane >> 2);
                const uint32_t* p = sAhh + r * 12 + kc;
                aH[mt][0] = p[0]; aH[mt][1] = p[96]; aH[mt][2] = p[4]; aH[mt][3] = p[100];
            }
#pragma unroll
            for (int nt = 0; nt < 10; nt++) {
                int n = wn * 80 + nt * 8 + (lane >> 2);
                const uint32_t* p = sBhh + n * 12 + kc;
                uint32_t b0 = p[0], b1 = p[4];
#pragma unroll
                for (int mt = 0; mt < 2; mt++)
                    mma_f16(acc[mt][nt], aH[mt], b0, b1);
            }
        }

        // ---- cross: two k16 MMAs (8 original k each)
#pragma unroll
        for (int ks = 0; ks < 2; ks++) {
            const int kc = ks * 8 + (lane & 3);
            uint32_t aX[2][4];
#pragma unroll
            for (int mt = 0; mt < 2; mt++) {
                int r = wm * 32 + mt * 16 + (lane >> 2);
                const uint32_t* p = sAx + r * 20 + kc;
                aX[mt][0] = p[0]; aX[mt][1] = p[160]; aX[mt][2] = p[4]; aX[mt][3] = p[164];
            }
#pragma unroll
            for (int nt = 0; nt < 10; nt++) {
                int n = wn * 80 + nt * 8 + (lane >> 2);
                const uint32_t* p = sBx + n * 20 + kc;
                uint32_t b0 = p[0], b1 = p[4];
#pragma unroll
                for (int mt = 0; mt < 2; mt++)
                    mma_f16(acc[mt][nt], aX[mt], b0, b1);
            }
        }
    }

    // epilogue (rows padded; cols < 480 <= LDC, padded cols harmless)
#pragma unroll
    for (int mt = 0; mt < 2; mt++) {
#pragma unroll
        for (int h = 0; h < 2; h++) {
            int r = row0 + wm * 32 + mt * 16 + (lane >> 2) + h * 8;
#pragma unroll
            for (int nt = 0; nt < 10; nt++) {
                int c = col0 + wn * 80 + nt * 8 + 2 * (lane & 3);
                float x = acc[mt][nt][h * 2 + 0];
                float y = acc[mt][nt][h * 2 + 1];
                size_t o = (size_t)r * LDC + c;
                if (MODE == 0) {
                    *(float2*)(C + o)  = make_float2(x, y);
                    *(float2*)(C2 + o) = make_float2(x > 0.f ? x : 0.f, y > 0.f ? y : 0.f);
                } else if (MODE == 1) {
                    float2 bm = *(const float2*)(biasM + o);
                    x += bm.x; y += bm.y;
                    *(float2*)(C + o) = make_float2(x > 0.f ? x : 0.f, y > 0.f ? y : 0.f);
                } else {
                    x += (c     < HIDDEN) ? biasV[c]     : 0.f;
                    y += (c + 1 < HIDDEN) ? biasV[c + 1] : 0.f;
                    *(float2*)(C + o) = make_float2(x > 0.f ? x : 0.f, y > 0.f ? y : 0.f);
                }
            }
        }
    }
}

// ---------------- per-molecule mean -----------------------------------------
__global__ __launch_bounds__(256)
void mol_mean_kernel(const float* __restrict__ ah, const int* __restrict__ mol_ids,
                     int n_atoms, float* __restrict__ out)
{
    const int m = blockIdx.x;
    __shared__ int s_start, s_end;
    if (threadIdx.x == 0) {
        int lo = 0, hi = n_atoms;
        while (lo < hi) { int mid = (lo + hi) >> 1; if (mol_ids[mid] <  m) lo = mid + 1; else hi = mid; }
        s_start = lo;
        lo = 0; hi = n_atoms;
        while (lo < hi) { int mid = (lo + hi) >> 1; if (mol_ids[mid] <= m) lo = mid + 1; else hi = mid; }
        s_end = lo;
    }
    __syncthreads();
    const int start = s_start;
    const int cnt   = s_end - s_start;
    const float inv = cnt > 0 ? 1.f / (float)cnt : 0.f;

    for (int h = threadIdx.x; h < HIDDEN; h += blockDim.x) {
        float s = 0.f;
        for (int a = 0; a < cnt; a++)
            s += ah[(size_t)(start + a) * LDC + h];
        out[(size_t)m * HIDDEN + h] = s * inv;
    }
}

// ---------------- launch ----------------------------------------------------
extern "C" void kernel_launch(void* const* d_in, const int* in_sizes, int n_in,
                              void* d_out, int out_size)
{
    const float* fatoms  = (const float*)d_in[0];
    const float* fbonds  = (const float*)d_in[1];
    const int*   agraph  = (const int*)d_in[2];
    const int*   bgraph  = (const int*)d_in[3];
    const int*   mol_ids = (const int*)d_in[4];
    const float* tree    = (const float*)d_in[6];
    const float* W_i     = (const float*)d_in[7];
    const float* W_h     = (const float*)d_in[8];
    const float* W_o     = (const float*)d_in[9];
    const float* b_o     = (const float*)d_in[10];
    float* out = (float*)d_out;

    const int n_atoms = in_sizes[0] / ATOM_FDIM;
    const int n_bonds = in_sizes[1] / (ATOM_FDIM + 5);
    const int n_mess  = in_sizes[6] / HIDDEN;
    const int n_mols  = out_size / HIDDEN;
    const int IN_FDIM = ATOM_FDIM + 5;       // 40
    const int OUT_K   = ATOM_FDIM + HIDDEN;  // 485 (src W_o ld)

    float *binput, *gmsg;
    uint32_t *neiHH, *neiX, *atHH, *atX, *fbHH, *fbX;
    uint32_t *WiHH, *WiX, *WhHH, *WhX, *WoHH, *WoX;
    cudaGetSymbolAddress((void**)&binput, g_binput);
    cudaGetSymbolAddress((void**)&gmsg,   g_gmsg);
    cudaGetSymbolAddress((void**)&neiHH,  g_neiHH);
    cudaGetSymbolAddress((void**)&neiX,   g_neiX);
    cudaGetSymbolAddress((void**)&atHH,   g_atHH);
    cudaGetSymbolAddress((void**)&atX,    g_atX);
    cudaGetSymbolAddress((void**)&fbHH,   g_fbHH);
    cudaGetSymbolAddress((void**)&fbX,    g_fbX);
    cudaGetSymbolAddress((void**)&WiHH,   g_WiHH);
    cudaGetSymbolAddress((void**)&WiX,    g_WiX);
    cudaGetSymbolAddress((void**)&WhHH,   g_WhHH);
    cudaGetSymbolAddress((void**)&WhX,    g_WhX);
    cudaGetSymbolAddress((void**)&WoHH,   g_WoHH);
    cudaGetSymbolAddress((void**)&WoX,    g_WoX);

    cudaFuncSetAttribute(mma_gemm<0>, cudaFuncAttributeMaxDynamicSharedMemorySize, SMEM_BYTES);
    cudaFuncSetAttribute(mma_gemm<1>, cudaFuncAttributeMaxDynamicSharedMemorySize, SMEM_BYTES);
    cudaFuncSetAttribute(mma_gemm<2>, cudaFuncAttributeMaxDynamicSharedMemorySize, SMEM_BYTES);

    dim3 blk(256);
    const int mb = (n_bonds + 127) / 128;   // 313
    const int ma = (n_atoms + 127) / 128;   // 157
    dim3 grid_b(3, mb), grid_a(3, ma);      // 3 x 160 = 480 cols

    // ---- pre-split inputs (SIDE 0) & weights (SIDE 1)
    split_pack<0><<<(n_bonds * ((IN_FDIM + 1) / 2) + 255) / 256, blk>>>(
        fbonds, IN_FDIM, n_bonds, IN_FDIM, fbHH, fbX, KI_PAD, 0);
    split_pack<1><<<(HIDDEN * ((IN_FDIM + 1) / 2) + 255) / 256, blk>>>(
        W_i, IN_FDIM, HIDDEN, IN_FDIM, WiHH, WiX, KI_PAD, 0);
    split_pack<1><<<(HIDDEN * ((HIDDEN + 1) / 2) + 255) / 256, blk>>>(
        W_h, HIDDEN, HIDDEN, HIDDEN, WhHH, WhX, KB_PAD, 0);
    // W_o permuted: [nei 450 | fatoms 35]
    split_pack<1><<<(HIDDEN * ((HIDDEN + 1) / 2) + 255) / 256, blk>>>(
        W_o + ATOM_FDIM, OUT_K, HIDDEN, HIDDEN, WoHH, WoX, KO_PAD, 0);
    split_pack<1><<<(HIDDEN * ((ATOM_FDIM + 1) / 2) + 255) / 256, blk>>>(
        W_o, OUT_K, HIDDEN, ATOM_FDIM, WoHH, WoX, KO_PAD, HIDDEN);
    // fatoms at k-offset 450
    split_pack<0><<<(n_atoms * ((ATOM_FDIM + 1) / 2) + 255) / 256, blk>>>(
        fatoms, ATOM_FDIM, n_atoms, ATOM_FDIM, atHH, atX, KO_PAD, HIDDEN);

    // ---- init layer: binput = fbonds @ W_i^T ; gmsg = relu(binput)
    mma_gemm<0><<<grid_b, blk, SMEM_BYTES>>>(fbHH, fbX, WiHH, WiX, KI_PAD, KI_PAD / 16,
                                             nullptr, nullptr, binput, gmsg);

    // ---- 5 message-passing steps
    for (int it = 0; it < 5; it++) {
        gather_split<<<n_bonds, blk>>>(bgraph, tree, n_mess, gmsg, neiHH, neiX, KB_PAD);
        mma_gemm<1><<<grid_b, blk, SMEM_BYTES>>>(neiHH, neiX, WhHH, WhX, KB_PAD, KB_PAD / 16,
                                                 binput, nullptr, gmsg, nullptr);
    }

    // ---- atom aggregation (nei at k 0..449) + output layer
    gather_split<<<n_atoms, blk>>>(agraph, tree, n_mess, gmsg, atHH, atX, KO_PAD);
    mma_gemm<2><<<grid_a, blk, SMEM_BYTES>>>(atHH, atX, WoHH, WoX, KO_PAD, KO_PAD / 16,
                                             nullptr, b_o, binput, nullptr);

    // ---- per-molecule mean
    mol_mean_kernel<<<n_mols, blk>>>(binput, mol_ids, n_atoms, out);
}